// round 16
// baseline (speedup 1.0000x reference)
#include <cuda_runtime.h>
#include <cstdint>

// Sampler: B=256 rows, V=128256 vocab.
//   temp == 0  -> argmax(logits)
//   temp  > 0  -> argmax(logits/temp - log(-log1p(-u)))   (Gumbel-max equivalence)
// log2-domain: score = l*invt - ln2*log2(|log2(1-u)|)  (same argmax; const dropped)
//
// TMA (cp.async.bulk) double-buffered pipeline: per CTA, 32 tiles x 5344B per
// stream staged through 2-stage static smem; tid0 produces, all threads
// consume after mbarrier parity-wait. Greedy rows skip the noise stream.
// 768 CTAs (3 chunks x 256 rows), last-CTA finalize, self-resetting scratch.
// OUTPUT: float32 tokens (exact: token < 2^24).

#define B_ROWS   256
#define VOCAB    128256
#define CHUNKS   3
#define NCTAS    (CHUNKS * B_ROWS)          // 768
#define NTHREADS 256
#define NWARPS   (NTHREADS / 32)
#define V4_TOT   (VOCAB / 4)                // 32064
#define PER      (V4_TOT / CHUNKS)          // 10688 (exact)
#define TILE_F4  334                        // 10688 = 32 * 334
#define TILE_B   (TILE_F4 * 16)             // 5344 bytes (16B multiple)
#define NTILES   32
#define NEG_INF  __int_as_float(0xff800000)
#define LN2F     0.69314718055994530942f

// Scratch: zero-initialized at module load; last CTA resets it each launch.
__device__ unsigned long long g_best[B_ROWS];
__device__ unsigned int       g_done;

// In-loop compare: strict greater only (indices monotone per accumulator ->
// keeping incumbent on ties IS the first-index tie-break).
__device__ __forceinline__ void take_fast(float& bv, int& bi, float v, int i) {
    if (v > bv) { bv = v; bi = i; }
}
// Merge-time compare: full argmax with first-index tie-break.
__device__ __forceinline__ void take_better(float& bv, int& bi, float v, int i) {
    if (v > bv || (v == bv && i < bi)) { bv = v; bi = i; }
}
// Monotone float -> u32 map (order-preserving incl. +/-inf)
__device__ __forceinline__ unsigned int fkey(float v) {
    unsigned int b = __float_as_uint(v);
    return b ^ ((b & 0x80000000u) ? 0xFFFFFFFFu : 0x80000000u);
}
__device__ __forceinline__ float gumbel_score(float l, float u, float invt) {
    // t = |log2(1-u)| ; score = l*invt - ln2*log2(t); u==0 -> +inf
    float m = __log2f(1.0f - u);
    float s = __log2f(fabsf(m));
    return fmaf(-LN2F, s, l * invt);
}

__device__ __forceinline__ uint32_t smem_u32(const void* p) {
    return (uint32_t)__cvta_generic_to_shared(p);
}
__device__ __forceinline__ void mbar_init(uint32_t a, uint32_t cnt) {
    asm volatile("mbarrier.init.shared.b64 [%0], %1;" :: "r"(a), "r"(cnt) : "memory");
}
__device__ __forceinline__ void mbar_expect_tx(uint32_t a, uint32_t bytes) {
    asm volatile("mbarrier.arrive.expect_tx.shared.b64 _, [%0], %1;"
                 :: "r"(a), "r"(bytes) : "memory");
}
__device__ __forceinline__ void bulk_g2s(uint32_t dst, const void* src,
                                         uint32_t bytes, uint32_t mbar) {
    asm volatile(
        "cp.async.bulk.shared::cluster.global.mbarrier::complete_tx::bytes "
        "[%0], [%1], %2, [%3];"
        :: "r"(dst), "l"(src), "r"(bytes), "r"(mbar) : "memory");
}
__device__ __forceinline__ void mbar_wait(uint32_t a, uint32_t phase) {
    asm volatile(
        "{\n\t.reg .pred P;\n\t"
        "WAIT_%=:\n\t"
        "mbarrier.try_wait.parity.acquire.cta.shared::cta.b64 P, [%0], %1, 0x989680;\n\t"
        "@P bra.uni DONE_%=;\n\t"
        "bra.uni WAIT_%=;\n\t"
        "DONE_%=:\n\t}"
        :: "r"(a), "r"(phase) : "memory");
}

__global__ __launch_bounds__(NTHREADS, 6)
void sampler_tma_kernel(const float* __restrict__ bigA,
                        const float* __restrict__ bigB,
                        const float* __restrict__ temps,
                        float* __restrict__ out) {
    __shared__ __align__(16) float4 sL[2][TILE_F4];
    __shared__ __align__(16) float4 sN[2][TILE_F4];
    __shared__ __align__(8)  unsigned long long mbar[2];

    const int row   = blockIdx.y;
    const int chunk = blockIdx.x;
    const int tid   = threadIdx.x;
    const int wid   = tid >> 5;
    const int lid   = tid & 31;

    // ---- input classification: 1 load/thread (P[miss] = 2^-256) ----
    int local = (__ldg(&bigA[tid]) < 0.0f);
    const int neg = __syncthreads_or(local);
    const float* __restrict__ logits = neg ? bigA : bigB;
    const float* __restrict__ noise  = neg ? bigB : bigA;

    const float temp   = temps[row];
    const bool  greedy = (temp == 0.0f);
    const float invt   = greedy ? 1.0f : (1.0f / temp);

    const float4* __restrict__ lp = (const float4*)(logits + (size_t)row * VOCAB);
    const float4* __restrict__ np = (const float4*)(noise  + (size_t)row * VOCAB);
    const int jbeg = chunk * PER;

    const uint32_t mb[2]  = { smem_u32(&mbar[0]), smem_u32(&mbar[1]) };
    const uint32_t dL[2]  = { smem_u32(&sL[0][0]), smem_u32(&sL[1][0]) };
    const uint32_t dN[2]  = { smem_u32(&sN[0][0]), smem_u32(&sN[1][0]) };
    const uint32_t xbytes = greedy ? TILE_B : 2 * TILE_B;

    if (tid == 0) {
        mbar_init(mb[0], 1);
        mbar_init(mb[1], 1);
    }
    __syncthreads();

    // prime both stages
    if (tid == 0) {
        #pragma unroll
        for (int t = 0; t < 2; t++) {
            mbar_expect_tx(mb[t], xbytes);
            bulk_g2s(dL[t], lp + jbeg + t * TILE_F4, TILE_B, mb[t]);
            if (!greedy)
                bulk_g2s(dN[t], np + jbeg + t * TILE_F4, TILE_B, mb[t]);
        }
    }

    // 4 independent accumulators (disjoint, monotone index sets)
    float bv0 = NEG_INF, bv1 = NEG_INF, bv2 = NEG_INF, bv3 = NEG_INF;
    int   bi0 = 0x7fffffff, bi1 = 0x7fffffff, bi2 = 0x7fffffff, bi3 = 0x7fffffff;

    for (int t = 0; t < NTILES; t++) {
        const int s = t & 1;
        mbar_wait(mb[s], (t >> 1) & 1);

        const int gbase = jbeg + t * TILE_F4;  // f4 index of tile start
        if (greedy) {
            for (int q = tid; q < TILE_F4; q += NTHREADS) {
                float4 l = sL[s][q];
                int i0 = 4 * (gbase + q);
                take_fast(bv0, bi0, l.x, i0);
                take_fast(bv1, bi1, l.y, i0 + 1);
                take_fast(bv2, bi2, l.z, i0 + 2);
                take_fast(bv3, bi3, l.w, i0 + 3);
            }
        } else {
            for (int q = tid; q < TILE_F4; q += NTHREADS) {
                float4 l = sL[s][q];
                float4 u = sN[s][q];
                int i0 = 4 * (gbase + q);
                take_fast(bv0, bi0, gumbel_score(l.x, u.x, invt), i0);
                take_fast(bv1, bi1, gumbel_score(l.y, u.y, invt), i0 + 1);
                take_fast(bv2, bi2, gumbel_score(l.z, u.z, invt), i0 + 2);
                take_fast(bv3, bi3, gumbel_score(l.w, u.w, invt), i0 + 3);
            }
        }
        __syncthreads();                  // everyone done reading stage s

        if (tid == 0 && t + 2 < NTILES) { // refill stage s with tile t+2
            mbar_expect_tx(mb[s], xbytes);
            bulk_g2s(dL[s], lp + jbeg + (t + 2) * TILE_F4, TILE_B, mb[s]);
            if (!greedy)
                bulk_g2s(dN[s], np + jbeg + (t + 2) * TILE_F4, TILE_B, mb[s]);
        }
    }

    // merge lane accumulators (tie -> lower index; full compare)
    float bv = bv0; int bi = bi0;
    take_better(bv, bi, bv1, bi1);
    take_better(bv, bi, bv2, bi2);
    take_better(bv, bi, bv3, bi3);

    // intra-warp reduce (value-max, min-index on ties)
    #pragma unroll
    for (int off = 16; off > 0; off >>= 1) {
        float ov = __shfl_down_sync(0xffffffffu, bv, off);
        int   oi = __shfl_down_sync(0xffffffffu, bi, off);
        take_better(bv, bi, ov, oi);
    }

    __shared__ float sv[NWARPS];
    __shared__ int   si[NWARPS];
    if (lid == 0) { sv[wid] = bv; si[wid] = bi; }
    __syncthreads();

    if (tid < 32) {
        bv = (lid < NWARPS) ? sv[lid] : NEG_INF;
        bi = (lid < NWARPS) ? si[lid] : 0x7fffffff;
        #pragma unroll
        for (int off = NWARPS / 2; off > 0; off >>= 1) {
            float ov = __shfl_down_sync(0xffffffffu, bv, off);
            int   oi = __shfl_down_sync(0xffffffffu, bi, off);
            take_better(bv, bi, ov, oi);
        }
        if (lid == 0) {
            // pack: high = monotone value key, low = ~index (min-index wins)
            unsigned long long key =
                ((unsigned long long)fkey(bv) << 32) | (unsigned int)(~bi);
            atomicMax(&g_best[row], key);
        }
    }

    // ---- last-CTA-done finalization ----
    __shared__ int is_last;
    __threadfence();                      // make our atomicMax visible first
    if (tid == 0) {
        unsigned int old = atomicAdd(&g_done, 1u);
        is_last = (old == NCTAS - 1);
    }
    __syncthreads();

    if (is_last) {
        __threadfence();                  // see all other CTAs' results
        if (tid < B_ROWS) {
            unsigned long long k = atomicMax(&g_best[tid], 0ull);
            unsigned int token = ~(unsigned int)(k & 0xFFFFFFFFull);
            out[tid] = (float)token;      // float32 tokens (exact < 2^24)
            g_best[tid] = 0ull;           // self-reset for next replay
        }
        __syncthreads();
        if (tid == 0) g_done = 0u;
        __threadfence();
    }
}

extern "C" void kernel_launch(void* const* d_in, const int* in_sizes, int n_in,
                              void* d_out, int out_size) {
    // temps = SMALLEST input; the two large inputs are classified on device.
    int smin = 0;
    for (int i = 1; i < n_in; i++)
        if (in_sizes[i] < in_sizes[smin]) smin = i;
    const float* temps = (const float*)d_in[smin];

    const float* big[2] = {nullptr, nullptr};
    int nbig = 0;
    for (int i = 0; i < n_in && nbig < 2; i++) {
        if (i == smin) continue;
        big[nbig++] = (const float*)d_in[i];
    }
    float* out = (float*)d_out;

    dim3 grid(CHUNKS, B_ROWS);
    sampler_tma_kernel<<<grid, NTHREADS>>>(big[0], big[1], temps, out);
}

// round 17
// speedup vs baseline: 1.0793x; 1.0793x over previous
#include <cuda_runtime.h>
#include <cstdint>

// Sampler: B=256 rows, V=128256 vocab.
//   temp == 0  -> argmax(logits)                          (reads logits only)
//   temp  > 0  -> argmax(logits/temp - log(-log1p(-u)))   (Gumbel-max equivalence)
// softmax unnecessary: argmax(softmax(s)/e) == argmax(s - log e).
//
// CHAMPION (R10): single-wave fused kernel. 768 CTAs (3 chunks x 256 rows),
// 6 CTAs/SM, x2 unroll with 4 LDG.128 batched ahead of compute per thread,
// 4 independent lane accumulators. Greedy CTAs skip the noise stream.
// Verified optimum across 7 architecture variants (R10-R16 sweep):
// occupancy/MLP/scheduling/ALU/TMA levers all neutral or regressed.
// Last-CTA-done finalization with self-resetting scratch.
// OUTPUT: float32 tokens (exact: token < 2^24).

#define B_ROWS   256
#define VOCAB    128256
#define CHUNKS   3
#define NCTAS    (CHUNKS * B_ROWS)          // 768
#define NTHREADS 256
#define NWARPS   (NTHREADS / 32)
#define V4_TOT   (VOCAB / 4)                // 32064
#define PER      (V4_TOT / CHUNKS)          // 10688 (exact)
#define NEG_INF  __int_as_float(0xff800000)

// Scratch: zero-initialized at module load; last CTA resets it each launch.
__device__ unsigned long long g_best[B_ROWS];
__device__ unsigned int       g_done;

__device__ __forceinline__ void take_better(float& bv, int& bi, float v, int i) {
    // argmax with first-index tie-break, matching jnp.argmax
    if (v > bv || (v == bv && i < bi)) { bv = v; bi = i; }
}

// Monotone float -> u32 map (order-preserving incl. +/-inf)
__device__ __forceinline__ unsigned int fkey(float v) {
    unsigned int b = __float_as_uint(v);
    return b ^ ((b & 0x80000000u) ? 0xFFFFFFFFu : 0x80000000u);
}

__device__ __forceinline__ float gumbel_score(float l, float u, float invt) {
    // score = l*invt - log(-log(1-u)); u==0 -> +inf (matches p/0 = inf)
    return fmaf(invt, l, -__logf(-__logf(1.0f - u)));
}

__global__ __launch_bounds__(NTHREADS, 6)
void sampler_fused_kernel(const float* __restrict__ bigA,
                          const float* __restrict__ bigB,
                          const float* __restrict__ temps,
                          float* __restrict__ out) {
    const int row   = blockIdx.y;
    const int chunk = blockIdx.x;
    const int tid   = threadIdx.x;

    // ---- input classification: 1 load/thread (P[miss] = 2^-256) ----
    int local = (__ldg(&bigA[tid]) < 0.0f);
    const int neg = __syncthreads_or(local);
    const float* __restrict__ logits = neg ? bigA : bigB;
    const float* __restrict__ noise  = neg ? bigB : bigA;

    const float temp   = temps[row];
    const bool  greedy = (temp == 0.0f);
    const float invt   = greedy ? 1.0f : (1.0f / temp);

    const float4* __restrict__ lp = (const float4*)(logits + (size_t)row * VOCAB);
    const float4* __restrict__ np = (const float4*)(noise  + (size_t)row * VOCAB);

    const int jbeg = chunk * PER;
    const int jend = jbeg + PER;

    // 4 independent accumulators (disjoint index sets) break the serial
    // compare chain; merged with index tie-break at the end.
    float bv0 = NEG_INF, bv1 = NEG_INF, bv2 = NEG_INF, bv3 = NEG_INF;
    int   bi0 = 0x7fffffff, bi1 = 0x7fffffff, bi2 = 0x7fffffff, bi3 = 0x7fffffff;

    if (greedy) {
        // greedy rows: pure argmax over logits, skip the noise stream entirely
        for (int j = jbeg + tid; j < jend; j += 2 * NTHREADS) {
            const int j1 = j + NTHREADS;
            const bool has1 = (j1 < jend);
            float4 a = __ldcs(&lp[j]);
            float4 b;
            if (has1) b = __ldcs(&lp[j1]);
            int i0 = 4 * j;
            take_better(bv0, bi0, a.x, i0);
            take_better(bv1, bi1, a.y, i0 + 1);
            take_better(bv2, bi2, a.z, i0 + 2);
            take_better(bv3, bi3, a.w, i0 + 3);
            if (has1) {
                int i1 = 4 * j1;
                take_better(bv0, bi0, b.x, i1);
                take_better(bv1, bi1, b.y, i1 + 1);
                take_better(bv2, bi2, b.z, i1 + 2);
                take_better(bv3, bi3, b.w, i1 + 3);
            }
        }
    } else {
        for (int j = jbeg + tid; j < jend; j += 2 * NTHREADS) {
            const int j1 = j + NTHREADS;
            const bool has1 = (j1 < jend);
            // batch all loads ahead of compute (4 LDG.128 in flight)
            float4 l0 = __ldcs(&lp[j]);
            float4 u0 = __ldcs(&np[j]);
            float4 l1, u1;
            if (has1) { l1 = __ldcs(&lp[j1]); u1 = __ldcs(&np[j1]); }

            int i0 = 4 * j;
            take_better(bv0, bi0, gumbel_score(l0.x, u0.x, invt), i0);
            take_better(bv1, bi1, gumbel_score(l0.y, u0.y, invt), i0 + 1);
            take_better(bv2, bi2, gumbel_score(l0.z, u0.z, invt), i0 + 2);
            take_better(bv3, bi3, gumbel_score(l0.w, u0.w, invt), i0 + 3);
            if (has1) {
                int i1 = 4 * j1;
                take_better(bv0, bi0, gumbel_score(l1.x, u1.x, invt), i1);
                take_better(bv1, bi1, gumbel_score(l1.y, u1.y, invt), i1 + 1);
                take_better(bv2, bi2, gumbel_score(l1.z, u1.z, invt), i1 + 2);
                take_better(bv3, bi3, gumbel_score(l1.w, u1.w, invt), i1 + 3);
            }
        }
    }

    // merge lane accumulators (indices disjoint; tie -> lower index)
    float bv = bv0; int bi = bi0;
    take_better(bv, bi, bv1, bi1);
    take_better(bv, bi, bv2, bi2);
    take_better(bv, bi, bv3, bi3);

    // intra-warp reduce (value-max, min-index on ties)
    #pragma unroll
    for (int off = 16; off > 0; off >>= 1) {
        float ov = __shfl_down_sync(0xffffffffu, bv, off);
        int   oi = __shfl_down_sync(0xffffffffu, bi, off);
        take_better(bv, bi, ov, oi);
    }

    __shared__ float sv[NWARPS];
    __shared__ int   si[NWARPS];
    const int wid = tid >> 5;
    const int lid = tid & 31;
    if (lid == 0) { sv[wid] = bv; si[wid] = bi; }
    __syncthreads();

    if (tid < 32) {
        bv = (lid < NWARPS) ? sv[lid] : NEG_INF;
        bi = (lid < NWARPS) ? si[lid] : 0x7fffffff;
        #pragma unroll
        for (int off = NWARPS / 2; off > 0; off >>= 1) {
            float ov = __shfl_down_sync(0xffffffffu, bv, off);
            int   oi = __shfl_down_sync(0xffffffffu, bi, off);
            take_better(bv, bi, ov, oi);
        }
        if (lid == 0) {
            // pack: high = monotone value key, low = ~index (min-index wins ties)
            unsigned long long key =
                ((unsigned long long)fkey(bv) << 32) | (unsigned int)(~bi);
            atomicMax(&g_best[row], key);
        }
    }

    // ---- last-CTA-done finalization ----
    __shared__ int is_last;
    __threadfence();                      // make our atomicMax visible first
    if (tid == 0) {
        unsigned int old = atomicAdd(&g_done, 1u);
        is_last = (old == NCTAS - 1);
    }
    __syncthreads();

    if (is_last) {
        __threadfence();                  // see all other CTAs' results
        if (tid < B_ROWS) {
            unsigned long long k = atomicMax(&g_best[tid], 0ull);
            unsigned int token = ~(unsigned int)(k & 0xFFFFFFFFull);
            out[tid] = (float)token;      // float32 tokens (exact < 2^24)
            g_best[tid] = 0ull;           // self-reset for next replay
        }
        __syncthreads();
        if (tid == 0) g_done = 0u;
        __threadfence();
    }
}

extern "C" void kernel_launch(void* const* d_in, const int* in_sizes, int n_in,
                              void* d_out, int out_size) {
    // temps = SMALLEST input; the two large inputs are classified on device.
    int smin = 0;
    for (int i = 1; i < n_in; i++)
        if (in_sizes[i] < in_sizes[smin]) smin = i;
    const float* temps = (const float*)d_in[smin];

    const float* big[2] = {nullptr, nullptr};
    int nbig = 0;
    for (int i = 0; i < n_in && nbig < 2; i++) {
        if (i == smin) continue;
        big[nbig++] = (const float*)d_in[i];
    }
    float* out = (float*)d_out;

    dim3 grid(CHUNKS, B_ROWS);
    sampler_fused_kernel<<<grid, NTHREADS>>>(big[0], big[1], temps, out);
}